// round 13
// baseline (speedup 1.0000x reference)
#include <cuda_runtime.h>
#include <cuda_bf16.h>

#define BB 8
#define FF 128
#define PP 256
#define TT 2048

__device__ __forceinline__ float ex2f(float x) {
    float r;
    asm("ex2.approx.f32 %0, %1;" : "=f"(r) : "f"(x));
    return r;
}

// warp-autonomous: warp owns 32 ticks x 32 pe-channels. No smem, no barriers.
// Inner loop processes flash PAIRS: two shfl/ex2/FMA bodies interleaved so the
// dependent chain covers two flashes per iteration.
__global__ __launch_bounds__(128, 7)
void flash_reco_kernel(const float* __restrict__ pe,     // [B,F,P]
                       const float* __restrict__ ftime,  // [B,F]
                       const float* __restrict__ conf,   // [B,F]
                       const float* __restrict__ sigma_ptr,
                       float* __restrict__ out)          // [B,P,T]
{
    const int lane = threadIdx.x & 31;
    const int warp = threadIdx.x >> 5;
    const int b    = blockIdx.z;
    const int p0   = blockIdx.y * 32;
    const int t0   = blockIdx.x * 128 + warp * 32;

    const float* __restrict__ base = pe + (size_t)(b * FF) * PP + p0;

    // cooperative prefetch: warm all 128 pe rows at this p0 (overlaps prefix RT)
    asm volatile("prefetch.global.L1 [%0];"
                 :: "l"(base + (warp * 32 + lane) * PP));

    const float sigma = sigma_ptr ? __ldg(sigma_ptr) : 1.0f;
    const float inv_s = 1.0f / sigma;
    const float W     = 6.0f * sigma;             // exp(-18) ~ 1.5e-8: negligible
    // interior normalizer: sigma*sqrt(2*pi); theta correction < 2.7e-9 @ sigma>=0.9
    const float inv_anorm = 1.0f / (sigma * 2.5066282746310002f + 1e-10f);
    const bool  analytic_ok = (sigma >= 0.9f);
    const float c2 = -0.72134752044448170f * inv_s * inv_s;  // -log2(e)/2 / s^2

    // ---- prefix: lane owns f = 4*lane+j; tb and lc = log2(conf/anorm) ----
    float4 tb4 = __ldg(reinterpret_cast<const float4*>(ftime + b * FF) + lane);
    float4 cf4 = __ldg(reinterpret_cast<const float4*>(conf  + b * FF) + lane);
    float tbs[4], lcs[4];
    tbs[0] = fminf(fmaxf(tb4.x * (float)TT, 0.0f), (float)(TT - 1));
    tbs[1] = fminf(fmaxf(tb4.y * (float)TT, 0.0f), (float)(TT - 1));
    tbs[2] = fminf(fmaxf(tb4.z * (float)TT, 0.0f), (float)(TT - 1));
    tbs[3] = fminf(fmaxf(tb4.w * (float)TT, 0.0f), (float)(TT - 1));
    lcs[0] = __log2f(cf4.x * inv_anorm);          // conf>=0: log2(0)=-inf -> w=0 ok
    lcs[1] = __log2f(cf4.y * inv_anorm);
    lcs[2] = __log2f(cf4.z * inv_anorm);
    lcs[3] = __log2f(cf4.w * inv_anorm);

    const float t_f = (float)(t0 + lane);
    const float wlo = (float)t0 - W;
    const float whi = (float)(t0 + 31) + W;
    const float elo = W, ehi = (float)(TT - 1) - W;

    unsigned long long acc[16];                   // 16 packed f32x2 = 32 p's
    #pragma unroll
    for (int j = 0; j < 16; ++j) acc[j] = 0ull;

    #pragma unroll
    for (int j = 0; j < 4; ++j) {
        unsigned mask =
            __ballot_sync(0xffffffffu, tbs[j] >= wlo && tbs[j] <= whi);
        while (mask) {
            // ---- extract a PAIR of flashes (ascending f: deterministic) ----
            const int k0 = __ffs(mask) - 1;  mask &= mask - 1;
            const bool two = (mask != 0);                    // warp-uniform
            const int k1 = two ? (__ffs(mask) - 1) : k0;
            if (two) mask &= mask - 1;

            float tb0 = __shfl_sync(0xffffffffu, tbs[j], k0);
            float lc0 = __shfl_sync(0xffffffffu, lcs[j], k0);
            float tb1 = __shfl_sync(0xffffffffu, tbs[j], k1);
            float lc1 = __shfl_sync(0xffffffffu, lcs[j], k1);

            // edge / small-sigma normalizer (rare, warp-uniform)
            if (!(analytic_ok && tb0 >= elo && tb0 <= ehi)) {
                const int lo = max(0, (int)ceilf(tb0 - W));
                const int hi = min(TT - 1, (int)floorf(tb0 + W));
                float s = 0.0f;
                for (int t = lo + lane; t <= hi; t += 32) {
                    const float zz = ((float)t - tb0) * inv_s;
                    s += __expf(-0.5f * zz * zz);
                }
                #pragma unroll
                for (int d = 16; d > 0; d >>= 1)
                    s += __shfl_xor_sync(0xffffffffu, s, d);
                lc0 = __log2f(__ldg(&conf[b * FF + 4 * k0 + j]) / (s + 1e-10f));
            }
            if (two && !(analytic_ok && tb1 >= elo && tb1 <= ehi)) {
                const int lo = max(0, (int)ceilf(tb1 - W));
                const int hi = min(TT - 1, (int)floorf(tb1 + W));
                float s = 0.0f;
                for (int t = lo + lane; t <= hi; t += 32) {
                    const float zz = ((float)t - tb1) * inv_s;
                    s += __expf(-0.5f * zz * zz);
                }
                #pragma unroll
                for (int d = 16; d > 0; d >>= 1)
                    s += __shfl_xor_sync(0xffffffffu, s, d);
                lc1 = __log2f(__ldg(&conf[b * FF + 4 * k1 + j]) / (s + 1e-10f));
            }

            // two independent weight chains (pipeline through MUFU)
            const float u0 = t_f - tb0;
            const float u1 = t_f - tb1;
            float w0 = ex2f(fmaf(u0 * c2, u0, lc0));
            float w1 = ex2f(fmaf(u1 * c2, u1, lc1));
            if (!two) w1 = 0.0f;   // inert: all contributions are >= +0.0
            unsigned long long ww0, ww1;
            asm("mov.b64 %0, {%1, %1};" : "=l"(ww0) : "f"(w0));
            asm("mov.b64 %0, {%1, %1};" : "=l"(ww1) : "f"(w1));

            const ulonglong2* r0 = reinterpret_cast<const ulonglong2*>(
                base + (4 * k0 + j) * PP);
            const ulonglong2* r1 = reinterpret_cast<const ulonglong2*>(
                base + (4 * k1 + j) * PP);        // == r0 when !two (L1-hot)

            #pragma unroll
            for (int q = 0; q < 8; ++q) {
                ulonglong2 v0 = __ldg(&r0[q]);    // both row streams independent
                ulonglong2 v1 = __ldg(&r1[q]);
                asm("fma.rn.f32x2 %0, %1, %2, %0;"
                    : "+l"(acc[2 * q])     : "l"(ww0), "l"(v0.x));
                asm("fma.rn.f32x2 %0, %1, %2, %0;"
                    : "+l"(acc[2 * q + 1]) : "l"(ww0), "l"(v0.y));
                asm("fma.rn.f32x2 %0, %1, %2, %0;"
                    : "+l"(acc[2 * q])     : "l"(ww1), "l"(v1.x));
                asm("fma.rn.f32x2 %0, %1, %2, %0;"
                    : "+l"(acc[2 * q + 1]) : "l"(ww1), "l"(v1.y));
            }
        }
    }

    // ---- stores: lanes span contiguous t -> coalesced 128B warp stores ----
    float* op = out + (size_t)(b * PP + p0) * TT + t0 + lane;
    #pragma unroll
    for (int j = 0; j < 16; ++j) {
        float lo, hi;
        asm("mov.b64 {%0, %1}, %2;" : "=f"(lo), "=f"(hi) : "l"(acc[j]));
        op[(size_t)(2 * j)     * TT] = lo;
        op[(size_t)(2 * j + 1) * TT] = hi;
    }
}

extern "C" void kernel_launch(void* const* d_in, const int* in_sizes, int n_in,
                              void* d_out, int out_size)
{
    const float* pe = (const float*)d_in[0];           // flashes_pe [B,F,P]
    const float* tm = (const float*)d_in[1];           // flashes_time [B,F,1]
    const float* cf = (const float*)d_in[2];           // flashes_confidence [B,F,1]
    const float* sg = (n_in >= 4) ? (const float*)d_in[n_in - 1] : nullptr;  // sigma last

    dim3 grid(TT / 128, PP / 32, BB);                  // 16 x 8 x 8 = 1024 blocks
    flash_reco_kernel<<<grid, 128>>>(pe, tm, cf, sg, (float*)d_out);
}

// round 14
// speedup vs baseline: 1.0844x; 1.0844x over previous
#include <cuda_runtime.h>
#include <cuda_bf16.h>

#define BB 8
#define FF 128
#define PP 256
#define TT 2048

__device__ __forceinline__ float ex2f(float x) {
    float r;
    asm("ex2.approx.f32 %0, %1;" : "=f"(r) : "f"(x));
    return r;
}

// warp-autonomous: warp owns 64 ticks x 32 pe-channels as TWO interleaved
// 32-tick sub-tiles sharing one flash loop: one shfl + one LDG stream per
// flash feeds two independent ex2/FMA chains (ILP-2). No smem, no barriers.
__global__ __launch_bounds__(128, 4)
void flash_reco_kernel(const float* __restrict__ pe,     // [B,F,P]
                       const float* __restrict__ ftime,  // [B,F]
                       const float* __restrict__ conf,   // [B,F]
                       const float* __restrict__ sigma_ptr,
                       float* __restrict__ out)          // [B,P,T]
{
    const int lane = threadIdx.x & 31;
    const int warp = threadIdx.x >> 5;
    const int b    = blockIdx.z;
    const int p0   = blockIdx.y * 32;
    const int t0   = blockIdx.x * 256 + warp * 64;       // 64 ticks per warp

    const float* __restrict__ base = pe + (size_t)(b * FF) * PP + p0;

    // cooperative prefetch: warm all 128 pe rows at this p0 (overlaps prefix RT)
    asm volatile("prefetch.global.L1 [%0];"
                 :: "l"(base + (warp * 32 + lane) * PP));

    const float sigma = sigma_ptr ? __ldg(sigma_ptr) : 1.0f;
    const float inv_s = 1.0f / sigma;
    const float W     = 6.0f * sigma;             // exp(-18) ~ 1.5e-8: negligible
    // interior normalizer: sigma*sqrt(2*pi); theta correction < 2.7e-9 @ sigma>=0.9
    const float inv_anorm = 1.0f / (sigma * 2.5066282746310002f + 1e-10f);
    const bool  analytic_ok = (sigma >= 0.9f);
    const float c2 = -0.72134752044448170f * inv_s * inv_s;  // -log2(e)/2 / s^2

    // ---- prefix: lane owns f = 4*lane+j; tb and lc = log2(conf/anorm) ----
    float4 tb4 = __ldg(reinterpret_cast<const float4*>(ftime + b * FF) + lane);
    float4 cf4 = __ldg(reinterpret_cast<const float4*>(conf  + b * FF) + lane);
    float tbs[4], lcs[4];
    tbs[0] = fminf(fmaxf(tb4.x * (float)TT, 0.0f), (float)(TT - 1));
    tbs[1] = fminf(fmaxf(tb4.y * (float)TT, 0.0f), (float)(TT - 1));
    tbs[2] = fminf(fmaxf(tb4.z * (float)TT, 0.0f), (float)(TT - 1));
    tbs[3] = fminf(fmaxf(tb4.w * (float)TT, 0.0f), (float)(TT - 1));
    lcs[0] = __log2f(cf4.x * inv_anorm);          // conf>=0: log2(0)=-inf -> w=0 ok
    lcs[1] = __log2f(cf4.y * inv_anorm);
    lcs[2] = __log2f(cf4.z * inv_anorm);
    lcs[3] = __log2f(cf4.w * inv_anorm);

    const float t_f = (float)(t0 + lane);                // sub0 tick; sub1 = +32
    const float wlo = (float)t0 - W;                     // union window
    const float whi = (float)(t0 + 63) + W;
    const float elo = W, ehi = (float)(TT - 1) - W;

    unsigned long long acc0[16], acc1[16];               // 2 x 16 packed f32x2
    #pragma unroll
    for (int j = 0; j < 16; ++j) { acc0[j] = 0ull; acc1[j] = 0ull; }

    #pragma unroll
    for (int j = 0; j < 4; ++j) {
        unsigned mask =
            __ballot_sync(0xffffffffu, tbs[j] >= wlo && tbs[j] <= whi);
        while (mask) {                            // ascending f: deterministic
            const int k = __ffs(mask) - 1;
            mask &= mask - 1;
            const float tbk = __shfl_sync(0xffffffffu, tbs[j], k);
            float lc = __shfl_sync(0xffffffffu, lcs[j], k);

            if (!(analytic_ok && tbk >= elo && tbk <= ehi)) {  // rare, uniform
                const int lo = max(0, (int)ceilf(tbk - W));
                const int hi = min(TT - 1, (int)floorf(tbk + W));
                float s = 0.0f;
                for (int t = lo + lane; t <= hi; t += 32) {
                    const float zz = ((float)t - tbk) * inv_s;
                    s += __expf(-0.5f * zz * zz);
                }
                #pragma unroll
                for (int d = 16; d > 0; d >>= 1)
                    s += __shfl_xor_sync(0xffffffffu, s, d);
                lc = __log2f(__ldg(&conf[b * FF + 4 * k + j]) / (s + 1e-10f));
            }

            // two independent weight chains from ONE shfl (u1 = u0 + 32)
            const float u0 = t_f - tbk;
            const float u1 = u0 + 32.0f;
            // out-of-window sub: arg <= -0.72*26^2 < -480 -> ex2 == +0.0 (inert)
            const float w0 = ex2f(fmaf(u0 * c2, u0, lc));
            const float w1 = ex2f(fmaf(u1 * c2, u1, lc));
            unsigned long long ww0, ww1;
            asm("mov.b64 %0, {%1, %1};" : "=l"(ww0) : "f"(w0));
            asm("mov.b64 %0, {%1, %1};" : "=l"(ww1) : "f"(w1));

            const ulonglong2* row = reinterpret_cast<const ulonglong2*>(
                base + (4 * k + j) * PP);         // ONE load stream, both subs
            #pragma unroll
            for (int q = 0; q < 8; ++q) {
                ulonglong2 v = __ldg(&row[q]);    // LDG.128 broadcast, L1-warm
                asm("fma.rn.f32x2 %0, %1, %2, %0;"
                    : "+l"(acc0[2 * q])     : "l"(ww0), "l"(v.x));
                asm("fma.rn.f32x2 %0, %1, %2, %0;"
                    : "+l"(acc0[2 * q + 1]) : "l"(ww0), "l"(v.y));
                asm("fma.rn.f32x2 %0, %1, %2, %0;"
                    : "+l"(acc1[2 * q])     : "l"(ww1), "l"(v.x));
                asm("fma.rn.f32x2 %0, %1, %2, %0;"
                    : "+l"(acc1[2 * q + 1]) : "l"(ww1), "l"(v.y));
            }
        }
    }

    // ---- stores: both sub-tiles, lanes span contiguous t (coalesced) ----
    float* op = out + (size_t)(b * PP + p0) * TT + t0 + lane;
    #pragma unroll
    for (int j = 0; j < 16; ++j) {
        float lo0, hi0, lo1, hi1;
        asm("mov.b64 {%0, %1}, %2;" : "=f"(lo0), "=f"(hi0) : "l"(acc0[j]));
        asm("mov.b64 {%0, %1}, %2;" : "=f"(lo1), "=f"(hi1) : "l"(acc1[j]));
        op[(size_t)(2 * j)     * TT]      = lo0;
        op[(size_t)(2 * j + 1) * TT]      = hi0;
        op[(size_t)(2 * j)     * TT + 32] = lo1;
        op[(size_t)(2 * j + 1) * TT + 32] = hi1;
    }
}

extern "C" void kernel_launch(void* const* d_in, const int* in_sizes, int n_in,
                              void* d_out, int out_size)
{
    const float* pe = (const float*)d_in[0];           // flashes_pe [B,F,P]
    const float* tm = (const float*)d_in[1];           // flashes_time [B,F,1]
    const float* cf = (const float*)d_in[2];           // flashes_confidence [B,F,1]
    const float* sg = (n_in >= 4) ? (const float*)d_in[n_in - 1] : nullptr;  // sigma last

    dim3 grid(TT / 256, PP / 32, BB);                  // 8 x 8 x 8 = 512 blocks
    flash_reco_kernel<<<grid, 128>>>(pe, tm, cf, sg, (float*)d_out);
}